// round 15
// baseline (speedup 1.0000x reference)
#include <cuda_runtime.h>
#include <cuda_fp16.h>
#include <math.h>
#include <cstdint>

#define NUM_E   8
#define BATCH   4
#define CCAP    1024
#define DMODEL  1024
#define DFF     4096

// CTA tile 128x256, BK=32; 16 warps in 2x8 grid, each warp 64x32. 512 threads.
#define BM 128
#define BN 256
#define BK 32
#define NSTAGE 3
#define NTHREADS 512

// fp16 smem tiles: 32 halfs (64B data) per row, padded to 80B for
// conflict-free fragment reads (bank = (r*20 + tq) mod 32, all distinct).
#define ROW_B       80
#define A_TILE_BYTES (BM * ROW_B)                     // 10240
#define B_TILE_BYTES (BN * ROW_B)                     // 20480
#define STAGE_BYTES  (A_TILE_BYTES + B_TILE_BYTES)    // 30720
#define SMEM_BYTES   (NSTAGE * STAGE_BYTES + 128)     // 92288

// 512 MB scratch: fp16 planes.
__device__ __align__(256) unsigned char g_scr[469762048];
#define OFF_IN  0
#define OFF_W1  67108864
#define OFF_W2  134217728
#define OFF_H   201326592

__device__ __forceinline__ uint32_t smem_u32(const void* p) {
    uint32_t a;
    asm("{ .reg .u64 t; cvta.to.shared.u64 t, %1; cvt.u32.u64 %0, t; }" : "=r"(a) : "l"(p));
    return a;
}
__device__ __forceinline__ void cp16(uint32_t dst, const void* src) {
    asm volatile("cp.async.cg.shared.global [%0], [%1], 16;"
                 :: "r"(dst), "l"(src) : "memory");
}
__device__ __forceinline__ void mma_f16(float acc[4], const unsigned a[4], const unsigned b[2]) {
    asm volatile(
        "mma.sync.aligned.m16n8k16.row.col.f32.f16.f16.f32 "
        "{%0,%1,%2,%3}, {%4,%5,%6,%7}, {%8,%9}, {%0,%1,%2,%3};\n"
        : "+f"(acc[0]), "+f"(acc[1]), "+f"(acc[2]), "+f"(acc[3])
        : "r"(a[0]), "r"(a[1]), "r"(a[2]), "r"(a[3]),
          "r"(b[0]), "r"(b[1]));
}
__device__ __forceinline__ float gelu_exact(float x) {
    return 0.5f * x * (1.0f + erff(x * 0.7071067811865476f));
}

// ---------------- pre-pass: fp32 -> fp16 plane ----------------
__global__ void __launch_bounds__(256, 8)
to_half_kernel(const float* __restrict__ src, __half* __restrict__ dst, int n4)
{
    int i = blockIdx.x * blockDim.x + threadIdx.x;
    int stride = gridDim.x * blockDim.x;
    for (; i < n4; i += stride) {
        float4 v = reinterpret_cast<const float4*>(src)[i];
        __half2 lo = __floats2half2_rn(v.x, v.y);
        __half2 hi = __floats2half2_rn(v.z, v.w);
        uint2 o;
        o.x = *reinterpret_cast<uint32_t*>(&lo);
        o.y = *reinterpret_cast<uint32_t*>(&hi);
        reinterpret_cast<uint2*>(dst)[i] = o;
    }
}

// ---------------- grouped NT GEMM, fp16 operands ----------------
// O[grp][m][n] = sum_k A[grp][m][k] * W[e][n][k] (+bias[e][n], opt gelu)
template<int NTOT, int KTOT, bool GELU>
__global__ void __launch_bounds__(NTHREADS, 1)
grouped_ffn(const __half* __restrict__ A0, const __half* __restrict__ W0,
            const float* __restrict__ bias0,
            float* __restrict__ Of, __half* __restrict__ Oh)
{
    extern __shared__ char smraw[];
    const uint32_t sm32 = (smem_u32(smraw) + 127u) & ~127u;
    const char*    smp  = smraw + (sm32 - smem_u32(smraw));

    const int tid  = threadIdx.x;
    const int wid  = tid >> 5;
    const int lane = tid & 31;
    const int wr   = wid >> 3;    // 0..1  (64-row slab)
    const int wc   = wid & 7;     // 0..7  (32-col slab)
    const int g    = lane >> 2;   // 0..7
    const int tq   = lane & 3;    // 0..3

    const int grp = blockIdx.z;
    const int e   = grp & (NUM_E - 1);
    const int bm  = blockIdx.y * BM;
    const int bn  = blockIdx.x * BN;

    const __half* A = A0 + (size_t)grp * CCAP * KTOT + (size_t)bm * KTOT;
    const __half* W = W0 + (size_t)e * NTOT * KTOT + (size_t)bn * KTOT;

    // ---- async-copy plan: chunk id -> row id>>2, 16B chunk id&3 (8 halfs) ----
    auto CP_TILE = [&](int kt, int s) {
        const size_t k0 = (size_t)kt * BK;
        const uint32_t abase = sm32 + s * STAGE_BYTES;
        {                                              // A: 512 chunks / 512 thr
            const int r = tid >> 2, c = tid & 3;
            cp16(abase + (uint32_t)r * ROW_B + c * 16,
                 A + (size_t)r * KTOT + k0 + c * 8);
        }
        const uint32_t bbase = abase + A_TILE_BYTES;
        #pragma unroll
        for (int i = 0; i < 2; ++i) {                  // B: 1024 chunks / 512 thr
            const int id = tid + i * NTHREADS;
            const int r  = id >> 2, c = id & 3;
            cp16(bbase + (uint32_t)r * ROW_B + c * 16,
                 W + (size_t)r * KTOT + k0 + c * 8);
        }
        asm volatile("cp.async.commit_group;" ::: "memory");
    };

    // ---- fragment plan (m16n8k16): element (r, k) at byte r*80 + k*2 ----
    const uint32_t aRow0 = (uint32_t)(wr * 64 + g) * ROW_B + tq * 4;  // + mi*16*80
    const uint32_t bRow0 = (uint32_t)(wc * 32 + g) * ROW_B + tq * 4;  // + ni*8*80

    float acc[4][4][4];
    #pragma unroll
    for (int mi = 0; mi < 4; ++mi)
        #pragma unroll
        for (int ni = 0; ni < 4; ++ni)
            #pragma unroll
            for (int c = 0; c < 4; ++c)
                acc[mi][ni][c] = 0.0f;

    auto COMPUTE = [&](const char* sbase) {
        #pragma unroll
        for (int kc = 0; kc < 2; ++kc) {              // two K=16 chunks
            const uint32_t ko = kc * 32;              // +32B per chunk
            unsigned af[4][4], bf[4][2];
            #pragma unroll
            for (int mi = 0; mi < 4; ++mi) {
                const char* base = sbase + aRow0 + mi * (16 * ROW_B) + ko;
                af[mi][0] = *reinterpret_cast<const unsigned*>(base);
                af[mi][1] = *reinterpret_cast<const unsigned*>(base + 8 * ROW_B);
                af[mi][2] = *reinterpret_cast<const unsigned*>(base + 16);
                af[mi][3] = *reinterpret_cast<const unsigned*>(base + 8 * ROW_B + 16);
            }
            #pragma unroll
            for (int ni = 0; ni < 4; ++ni) {
                const char* base = sbase + A_TILE_BYTES + bRow0 + ni * (8 * ROW_B) + ko;
                bf[ni][0] = *reinterpret_cast<const unsigned*>(base);
                bf[ni][1] = *reinterpret_cast<const unsigned*>(base + 16);
            }
            #pragma unroll
            for (int mi = 0; mi < 4; ++mi)
                #pragma unroll
                for (int ni = 0; ni < 4; ++ni)
                    mma_f16(acc[mi][ni], af[mi], bf[ni]);
        }
    };

    const int NK = KTOT / BK;

    CP_TILE(0, 0);
    CP_TILE(1, 1);

    int s_cur = 0, s_nxt = 2;

    #pragma unroll 1
    for (int kt = 0; kt < NK; ++kt) {
        if (kt + 1 < NK) asm volatile("cp.async.wait_group 1;" ::: "memory");
        else             asm volatile("cp.async.wait_group 0;" ::: "memory");
        __syncthreads();

        if (kt + 2 < NK) CP_TILE(kt + 2, s_nxt);

        COMPUTE(smp + s_cur * STAGE_BYTES);

        s_cur = (s_cur + 1 == NSTAGE) ? 0 : s_cur + 1;
        s_nxt = (s_nxt + 1 == NSTAGE) ? 0 : s_nxt + 1;
    }

    // Epilogue
    const float* bias = bias0 + (size_t)e * NTOT + bn;

    #pragma unroll
    for (int mi = 0; mi < 4; ++mi) {
        const int r0 = bm + wr * 64 + mi * 16 + g;
        #pragma unroll
        for (int ni = 0; ni < 4; ++ni) {
            const int cc = wc * 32 + ni * 8 + tq * 2;
            const float2 bv = *reinterpret_cast<const float2*>(bias + cc);
            float v00 = acc[mi][ni][0] + bv.x;
            float v01 = acc[mi][ni][1] + bv.y;
            float v10 = acc[mi][ni][2] + bv.x;
            float v11 = acc[mi][ni][3] + bv.y;
            if (GELU) {
                v00 = gelu_exact(v00); v01 = gelu_exact(v01);
                v10 = gelu_exact(v10); v11 = gelu_exact(v11);
                __half* H = Oh + (size_t)grp * CCAP * NTOT + bn;
                __half2 p0 = __floats2half2_rn(v00, v01);
                __half2 p1 = __floats2half2_rn(v10, v11);
                *reinterpret_cast<__half2*>(H + (size_t)r0 * NTOT + cc)       = p0;
                *reinterpret_cast<__half2*>(H + (size_t)(r0 + 8) * NTOT + cc) = p1;
            } else {
                float* O = Of + (size_t)grp * CCAP * NTOT + bn;
                *reinterpret_cast<float2*>(O + (size_t)r0 * NTOT + cc)       = make_float2(v00, v01);
                *reinterpret_cast<float2*>(O + (size_t)(r0 + 8) * NTOT + cc) = make_float2(v10, v11);
            }
        }
    }
}

extern "C" void kernel_launch(void* const* d_in, const int* in_sizes, int n_in,
                              void* d_out, int out_size)
{
    const float* inputs = (const float*)d_in[0];  // [4, 8192, 1024]
    const float* w1     = (const float*)d_in[1];  // [8, 4096, 1024]
    const float* b1     = (const float*)d_in[2];  // [8, 4096]
    const float* w2     = (const float*)d_in[3];  // [8, 1024, 4096]
    const float* b2     = (const float*)d_in[4];  // [8, 1024]
    float*       out    = (float*)d_out;          // [4, 8192, 1024]

    void* sp = nullptr;
    cudaGetSymbolAddress(&sp, g_scr);
    __half* in_h = (__half*)((char*)sp + OFF_IN);
    __half* w1_h = (__half*)((char*)sp + OFF_W1);
    __half* w2_h = (__half*)((char*)sp + OFF_W2);
    __half* h_h  = (__half*)((char*)sp + OFF_H);

    // Pre-pass: fp32 -> fp16 planes (each 33,554,432 elems = 8,388,608 float4)
    const int N4 = 8388608;
    to_half_kernel<<<2048, 256>>>(inputs, in_h, N4);
    to_half_kernel<<<2048, 256>>>(w1,     w1_h, N4);
    to_half_kernel<<<2048, 256>>>(w2,     w2_h, N4);

    cudaFuncSetAttribute(grouped_ffn<DFF, DMODEL, true>,
                         cudaFuncAttributeMaxDynamicSharedMemorySize, SMEM_BYTES);
    cudaFuncSetAttribute(grouped_ffn<DMODEL, DFF, false>,
                         cudaFuncAttributeMaxDynamicSharedMemorySize, SMEM_BYTES);

    // GEMM1 + gelu: h[grp][c][f]  (32 groups, M=1024, N=4096, K=1024), fp16 out
    {
        dim3 grid(DFF / BN, CCAP / BM, BATCH * NUM_E);
        grouped_ffn<DFF, DMODEL, true><<<grid, NTHREADS, SMEM_BYTES>>>(
            in_h, w1_h, b1, nullptr, h_h);
    }
    // GEMM2: out[grp][c][d]  (32 groups, M=1024, N=1024, K=4096), fp32 out
    {
        dim3 grid(DMODEL / BN, CCAP / BM, BATCH * NUM_E);
        grouped_ffn<DMODEL, DFF, false><<<grid, NTHREADS, SMEM_BYTES>>>(
            h_h, w2_h, b2, out, nullptr);
    }
}

// round 16
// speedup vs baseline: 1.4609x; 1.4609x over previous
#include <cuda_runtime.h>
#include <cuda_fp16.h>
#include <math.h>
#include <cstdint>

#define NUM_E   8
#define BATCH   4
#define CCAP    1024
#define DMODEL  1024
#define DFF     4096

// CTA tile 128x256, BK=64; 8 warps in 2x4 grid, each warp 64x64. 256 threads.
#define BM 128
#define BN 256
#define BK 64
#define NSTAGE 3
#define NTHREADS 256

// fp16 smem tiles: 64 halfs (128B data) per row, padded to 144B.
// Fragment-read banks: (g*144/4 + tq) mod 32 = 4g+tq -> all 32 distinct.
#define ROW_B       144
#define A_TILE_BYTES (BM * ROW_B)                     // 18432
#define B_TILE_BYTES (BN * ROW_B)                     // 36864
#define STAGE_BYTES  (A_TILE_BYTES + B_TILE_BYTES)    // 55296
#define SMEM_BYTES   (NSTAGE * STAGE_BYTES + 128)     // 166016

// 512 MB scratch: fp16 planes.
__device__ __align__(256) unsigned char g_scr[469762048];
#define OFF_IN  0
#define OFF_W1  67108864
#define OFF_W2  134217728
#define OFF_H   201326592

__device__ __forceinline__ uint32_t smem_u32(const void* p) {
    uint32_t a;
    asm("{ .reg .u64 t; cvta.to.shared.u64 t, %1; cvt.u32.u64 %0, t; }" : "=r"(a) : "l"(p));
    return a;
}
__device__ __forceinline__ void cp16(uint32_t dst, const void* src) {
    asm volatile("cp.async.cg.shared.global [%0], [%1], 16;"
                 :: "r"(dst), "l"(src) : "memory");
}
__device__ __forceinline__ void mma_f16(float acc[4], const unsigned a[4], const unsigned b[2]) {
    asm volatile(
        "mma.sync.aligned.m16n8k16.row.col.f32.f16.f16.f32 "
        "{%0,%1,%2,%3}, {%4,%5,%6,%7}, {%8,%9}, {%0,%1,%2,%3};\n"
        : "+f"(acc[0]), "+f"(acc[1]), "+f"(acc[2]), "+f"(acc[3])
        : "r"(a[0]), "r"(a[1]), "r"(a[2]), "r"(a[3]),
          "r"(b[0]), "r"(b[1]));
}
__device__ __forceinline__ float gelu_exact(float x) {
    return 0.5f * x * (1.0f + erff(x * 0.7071067811865476f));
}

// ---------------- pre-pass: fp32 -> fp16 plane ----------------
__global__ void __launch_bounds__(256, 8)
to_half_kernel(const float* __restrict__ src, __half* __restrict__ dst, int n4)
{
    int i = blockIdx.x * blockDim.x + threadIdx.x;
    int stride = gridDim.x * blockDim.x;
    for (; i < n4; i += stride) {
        float4 v = reinterpret_cast<const float4*>(src)[i];
        __half2 lo = __floats2half2_rn(v.x, v.y);
        __half2 hi = __floats2half2_rn(v.z, v.w);
        uint2 o;
        o.x = *reinterpret_cast<uint32_t*>(&lo);
        o.y = *reinterpret_cast<uint32_t*>(&hi);
        reinterpret_cast<uint2*>(dst)[i] = o;
    }
}

// ---------------- grouped NT GEMM, fp16 operands ----------------
// O[grp][m][n] = sum_k A[grp][m][k] * W[e][n][k] (+bias[e][n], opt gelu)
template<int NTOT, int KTOT, bool GELU>
__global__ void __launch_bounds__(NTHREADS, 1)
grouped_ffn(const __half* __restrict__ A0, const __half* __restrict__ W0,
            const float* __restrict__ bias0,
            float* __restrict__ Of, __half* __restrict__ Oh)
{
    extern __shared__ char smraw[];
    const uint32_t sm32 = (smem_u32(smraw) + 127u) & ~127u;
    const char*    smp  = smraw + (sm32 - smem_u32(smraw));

    const int tid  = threadIdx.x;
    const int wid  = tid >> 5;
    const int lane = tid & 31;
    const int wr   = wid >> 2;    // 0..1  (64-row slab)
    const int wc   = wid & 3;     // 0..3  (64-col slab)
    const int g    = lane >> 2;   // 0..7
    const int tq   = lane & 3;    // 0..3

    const int grp = blockIdx.z;
    const int e   = grp & (NUM_E - 1);
    const int bm  = blockIdx.y * BM;
    const int bn  = blockIdx.x * BN;

    const __half* A = A0 + (size_t)grp * CCAP * KTOT + (size_t)bm * KTOT;
    const __half* W = W0 + (size_t)e * NTOT * KTOT + (size_t)bn * KTOT;

    // ---- async-copy plan: chunk id -> row id>>3, 16B chunk id&7 (8 halfs) ----
    // A: 128 rows x 8 chunks = 1024; B: 256 x 8 = 2048. 12 cp16/thread/iter.
    auto CP_A = [&](int kt, int s) {
        const size_t k0 = (size_t)kt * BK;
        const uint32_t abase = sm32 + s * STAGE_BYTES;
        #pragma unroll
        for (int i = 0; i < 4; ++i) {
            const int id = tid + i * NTHREADS;
            const int r  = id >> 3, c = id & 7;
            cp16(abase + (uint32_t)r * ROW_B + c * 16,
                 A + (size_t)r * KTOT + k0 + c * 8);
        }
    };
    auto CP_B = [&](int kt, int s, int half) {
        const size_t k0 = (size_t)kt * BK;
        const uint32_t bbase = sm32 + s * STAGE_BYTES + A_TILE_BYTES;
        #pragma unroll
        for (int i = 0; i < 4; ++i) {
            const int id = tid + (i + half * 4) * NTHREADS;
            const int r  = id >> 3, c = id & 7;
            cp16(bbase + (uint32_t)r * ROW_B + c * 16,
                 W + (size_t)r * KTOT + k0 + c * 8);
        }
    };
    auto CP_COMMIT = [&]() {
        asm volatile("cp.async.commit_group;" ::: "memory");
    };

    // ---- fragment plan (m16n8k16): element (r, k) at byte r*144 + k*2 ----
    const uint32_t aRow0 = (uint32_t)(wr * 64 + g) * ROW_B + tq * 4;  // + mi*16*144
    const uint32_t bRow0 = (uint32_t)(wc * 64 + g) * ROW_B + tq * 4;  // + ni*8*144

    float acc[4][8][4];
    #pragma unroll
    for (int mi = 0; mi < 4; ++mi)
        #pragma unroll
        for (int ni = 0; ni < 8; ++ni)
            #pragma unroll
            for (int c = 0; c < 4; ++c)
                acc[mi][ni][c] = 0.0f;

    auto COMPUTE_KC = [&](const char* sbase, int kc) {
        const uint32_t ko = kc * 32;                  // 16 k = 32B per chunk
        unsigned af[4][4], bf[8][2];
        #pragma unroll
        for (int mi = 0; mi < 4; ++mi) {
            const char* base = sbase + aRow0 + mi * (16 * ROW_B) + ko;
            af[mi][0] = *reinterpret_cast<const unsigned*>(base);
            af[mi][1] = *reinterpret_cast<const unsigned*>(base + 8 * ROW_B);
            af[mi][2] = *reinterpret_cast<const unsigned*>(base + 16);
            af[mi][3] = *reinterpret_cast<const unsigned*>(base + 8 * ROW_B + 16);
        }
        #pragma unroll
        for (int ni = 0; ni < 8; ++ni) {
            const char* base = sbase + A_TILE_BYTES + bRow0 + ni * (8 * ROW_B) + ko;
            bf[ni][0] = *reinterpret_cast<const unsigned*>(base);
            bf[ni][1] = *reinterpret_cast<const unsigned*>(base + 16);
        }
        #pragma unroll
        for (int mi = 0; mi < 4; ++mi)
            #pragma unroll
            for (int ni = 0; ni < 8; ++ni)
                mma_f16(acc[mi][ni], af[mi], bf[ni]);
    };

    const int NK = KTOT / BK;

    // Prologue: stages 0,1 in flight
    CP_A(0, 0); CP_B(0, 0, 0); CP_B(0, 0, 1); CP_COMMIT();
    CP_A(1, 1); CP_B(1, 1, 0); CP_B(1, 1, 1); CP_COMMIT();

    int s_cur = 0, s_nxt = 2;

    #pragma unroll 1
    for (int kt = 0; kt < NK; ++kt) {
        if (kt + 1 < NK) asm volatile("cp.async.wait_group 1;" ::: "memory");
        else             asm volatile("cp.async.wait_group 0;" ::: "memory");
        __syncthreads();

        const char* sbase = smp + s_cur * STAGE_BYTES;
        const bool more = (kt + 2 < NK);

        // Interleave next-stage copies between kc chunks (no register staging).
        COMPUTE_KC(sbase, 0);
        if (more) CP_A(kt + 2, s_nxt);
        COMPUTE_KC(sbase, 1);
        if (more) CP_B(kt + 2, s_nxt, 0);
        COMPUTE_KC(sbase, 2);
        if (more) { CP_B(kt + 2, s_nxt, 1); CP_COMMIT(); }
        COMPUTE_KC(sbase, 3);

        s_cur = (s_cur + 1 == NSTAGE) ? 0 : s_cur + 1;
        s_nxt = (s_nxt + 1 == NSTAGE) ? 0 : s_nxt + 1;
    }

    // Epilogue
    const float* bias = bias0 + (size_t)e * NTOT + bn;

    #pragma unroll
    for (int mi = 0; mi < 4; ++mi) {
        const int r0 = bm + wr * 64 + mi * 16 + g;
        #pragma unroll
        for (int ni = 0; ni < 8; ++ni) {
            const int cc = wc * 64 + ni * 8 + tq * 2;
            const float2 bv = *reinterpret_cast<const float2*>(bias + cc);
            float v00 = acc[mi][ni][0] + bv.x;
            float v01 = acc[mi][ni][1] + bv.y;
            float v10 = acc[mi][ni][2] + bv.x;
            float v11 = acc[mi][ni][3] + bv.y;
            if (GELU) {
                v00 = gelu_exact(v00); v01 = gelu_exact(v01);
                v10 = gelu_exact(v10); v11 = gelu_exact(v11);
                __half* H = Oh + (size_t)grp * CCAP * NTOT + bn;
                __half2 p0 = __floats2half2_rn(v00, v01);
                __half2 p1 = __floats2half2_rn(v10, v11);
                *reinterpret_cast<__half2*>(H + (size_t)r0 * NTOT + cc)       = p0;
                *reinterpret_cast<__half2*>(H + (size_t)(r0 + 8) * NTOT + cc) = p1;
            } else {
                float* O = Of + (size_t)grp * CCAP * NTOT + bn;
                *reinterpret_cast<float2*>(O + (size_t)r0 * NTOT + cc)       = make_float2(v00, v01);
                *reinterpret_cast<float2*>(O + (size_t)(r0 + 8) * NTOT + cc) = make_float2(v10, v11);
            }
        }
    }
}

extern "C" void kernel_launch(void* const* d_in, const int* in_sizes, int n_in,
                              void* d_out, int out_size)
{
    const float* inputs = (const float*)d_in[0];  // [4, 8192, 1024]
    const float* w1     = (const float*)d_in[1];  // [8, 4096, 1024]
    const float* b1     = (const float*)d_in[2];  // [8, 4096]
    const float* w2     = (const float*)d_in[3];  // [8, 1024, 4096]
    const float* b2     = (const float*)d_in[4];  // [8, 1024]
    float*       out    = (float*)d_out;          // [4, 8192, 1024]

    void* sp = nullptr;
    cudaGetSymbolAddress(&sp, g_scr);
    __half* in_h = (__half*)((char*)sp + OFF_IN);
    __half* w1_h = (__half*)((char*)sp + OFF_W1);
    __half* w2_h = (__half*)((char*)sp + OFF_W2);
    __half* h_h  = (__half*)((char*)sp + OFF_H);

    // Pre-pass: fp32 -> fp16 planes (each 33,554,432 elems = 8,388,608 float4)
    const int N4 = 8388608;
    to_half_kernel<<<2048, 256>>>(inputs, in_h, N4);
    to_half_kernel<<<2048, 256>>>(w1,     w1_h, N4);
    to_half_kernel<<<2048, 256>>>(w2,     w2_h, N4);

    cudaFuncSetAttribute(grouped_ffn<DFF, DMODEL, true>,
                         cudaFuncAttributeMaxDynamicSharedMemorySize, SMEM_BYTES);
    cudaFuncSetAttribute(grouped_ffn<DMODEL, DFF, false>,
                         cudaFuncAttributeMaxDynamicSharedMemorySize, SMEM_BYTES);

    // GEMM1 + gelu: h[grp][c][f]  (32 groups, M=1024, N=4096, K=1024), fp16 out
    {
        dim3 grid(DFF / BN, CCAP / BM, BATCH * NUM_E);
        grouped_ffn<DFF, DMODEL, true><<<grid, NTHREADS, SMEM_BYTES>>>(
            in_h, w1_h, b1, nullptr, h_h);
    }
    // GEMM2: out[grp][c][d]  (32 groups, M=1024, N=1024, K=4096), fp32 out
    {
        dim3 grid(DMODEL / BN, CCAP / BM, BATCH * NUM_E);
        grouped_ffn<DMODEL, DFF, false><<<grid, NTHREADS, SMEM_BYTES>>>(
            h_h, w2_h, b2, out, nullptr);
    }
}

// round 17
// speedup vs baseline: 1.5396x; 1.0539x over previous
#include <cuda_runtime.h>
#include <cuda_fp16.h>
#include <math.h>
#include <cstdint>

#define NUM_E   8
#define BATCH   4
#define CCAP    1024
#define DMODEL  1024
#define DFF     4096

// CTA tile 128x256, BK=128; 8 warps in 2x4 grid, each warp 64x64. 256 threads.
#define BM 128
#define BN 256
#define BK 128
#define NSTAGE 2
#define NTHREADS 256

// fp16 smem tiles: 128 halfs (256B data) per row, padded to 272B.
// Fragment-read banks: (g*68 + tq) mod 32 = 4g+tq -> all 32 distinct.
#define ROW_B       272
#define A_TILE_BYTES (BM * ROW_B)                     // 34816
#define B_TILE_BYTES (BN * ROW_B)                     // 69632
#define STAGE_BYTES  (A_TILE_BYTES + B_TILE_BYTES)    // 104448
#define SMEM_BYTES   (NSTAGE * STAGE_BYTES + 128)     // 209024

// 512 MB scratch: fp16 planes.
__device__ __align__(256) unsigned char g_scr[469762048];
#define OFF_IN  0
#define OFF_W1  67108864
#define OFF_W2  134217728
#define OFF_H   201326592

__device__ __forceinline__ uint32_t smem_u32(const void* p) {
    uint32_t a;
    asm("{ .reg .u64 t; cvta.to.shared.u64 t, %1; cvt.u32.u64 %0, t; }" : "=r"(a) : "l"(p));
    return a;
}
__device__ __forceinline__ void cp16(uint32_t dst, const void* src) {
    asm volatile("cp.async.cg.shared.global [%0], [%1], 16;"
                 :: "r"(dst), "l"(src) : "memory");
}
__device__ __forceinline__ void mma_f16(float acc[4], const unsigned a[4], const unsigned b[2]) {
    asm volatile(
        "mma.sync.aligned.m16n8k16.row.col.f32.f16.f16.f32 "
        "{%0,%1,%2,%3}, {%4,%5,%6,%7}, {%8,%9}, {%0,%1,%2,%3};\n"
        : "+f"(acc[0]), "+f"(acc[1]), "+f"(acc[2]), "+f"(acc[3])
        : "r"(a[0]), "r"(a[1]), "r"(a[2]), "r"(a[3]),
          "r"(b[0]), "r"(b[1]));
}
__device__ __forceinline__ float gelu_exact(float x) {
    return 0.5f * x * (1.0f + erff(x * 0.7071067811865476f));
}

// ---------------- pre-pass: fp32 -> fp16 plane ----------------
__global__ void __launch_bounds__(256, 8)
to_half_kernel(const float* __restrict__ src, __half* __restrict__ dst, int n4)
{
    int i = blockIdx.x * blockDim.x + threadIdx.x;
    int stride = gridDim.x * blockDim.x;
    for (; i < n4; i += stride) {
        float4 v = reinterpret_cast<const float4*>(src)[i];
        __half2 lo = __floats2half2_rn(v.x, v.y);
        __half2 hi = __floats2half2_rn(v.z, v.w);
        uint2 o;
        o.x = *reinterpret_cast<uint32_t*>(&lo);
        o.y = *reinterpret_cast<uint32_t*>(&hi);
        reinterpret_cast<uint2*>(dst)[i] = o;
    }
}

// ---------------- grouped NT GEMM, fp16 operands ----------------
// O[grp][m][n] = sum_k A[grp][m][k] * W[e][n][k] (+bias[e][n], opt gelu)
template<int NTOT, int KTOT, bool GELU>
__global__ void __launch_bounds__(NTHREADS, 1)
grouped_ffn(const __half* __restrict__ A0, const __half* __restrict__ W0,
            const float* __restrict__ bias0,
            float* __restrict__ Of, __half* __restrict__ Oh)
{
    extern __shared__ char smraw[];
    const uint32_t sm32 = (smem_u32(smraw) + 127u) & ~127u;
    const char*    smp  = smraw + (sm32 - smem_u32(smraw));

    const int tid  = threadIdx.x;
    const int wid  = tid >> 5;
    const int lane = tid & 31;
    const int wr   = wid >> 2;    // 0..1  (64-row slab)
    const int wc   = wid & 3;     // 0..3  (64-col slab)
    const int g    = lane >> 2;   // 0..7
    const int tq   = lane & 3;    // 0..3

    const int grp = blockIdx.z;
    const int e   = grp & (NUM_E - 1);
    const int bm  = blockIdx.y * BM;
    const int bn  = blockIdx.x * BN;

    const __half* A = A0 + (size_t)grp * CCAP * KTOT + (size_t)bm * KTOT;
    const __half* W = W0 + (size_t)e * NTOT * KTOT + (size_t)bn * KTOT;

    // ---- async-copy plan: chunk id -> row id>>4, 16B chunk id&15 (8 halfs) ----
    // A: 128 rows x 16 chunks = 2048 -> 8/thread; B: 256 x 16 = 4096 -> 16/thread.
    auto CP_A = [&](int kt, int s, int part) {       // part 0..1, 4 chunks each
        const size_t k0 = (size_t)kt * BK;
        const uint32_t abase = sm32 + s * STAGE_BYTES;
        #pragma unroll
        for (int i = 0; i < 4; ++i) {
            const int id = tid + (i + part * 4) * NTHREADS;
            const int r  = id >> 4, c = id & 15;
            cp16(abase + (uint32_t)r * ROW_B + c * 16,
                 A + (size_t)r * KTOT + k0 + c * 8);
        }
    };
    auto CP_B = [&](int kt, int s, int part) {       // part 0..3, 4 chunks each
        const size_t k0 = (size_t)kt * BK;
        const uint32_t bbase = sm32 + s * STAGE_BYTES + A_TILE_BYTES;
        #pragma unroll
        for (int i = 0; i < 4; ++i) {
            const int id = tid + (i + part * 4) * NTHREADS;
            const int r  = id >> 4, c = id & 15;
            cp16(bbase + (uint32_t)r * ROW_B + c * 16,
                 W + (size_t)r * KTOT + k0 + c * 8);
        }
    };
    auto CP_COMMIT = [&]() {
        asm volatile("cp.async.commit_group;" ::: "memory");
    };

    // ---- fragment plan (m16n8k16): element (r, k) at byte r*272 + k*2 ----
    const uint32_t aRow0 = (uint32_t)(wr * 64 + g) * ROW_B + tq * 4;  // + mi*16*272
    const uint32_t bRow0 = (uint32_t)(wc * 64 + g) * ROW_B + tq * 4;  // + ni*8*272

    float acc[4][8][4];
    #pragma unroll
    for (int mi = 0; mi < 4; ++mi)
        #pragma unroll
        for (int ni = 0; ni < 8; ++ni)
            #pragma unroll
            for (int c = 0; c < 4; ++c)
                acc[mi][ni][c] = 0.0f;

    auto COMPUTE_KC = [&](const char* sbase, int kc) {
        const uint32_t ko = kc * 32;                  // 16 k = 32B per chunk
        unsigned af[4][4], bf[8][2];
        #pragma unroll
        for (int mi = 0; mi < 4; ++mi) {
            const char* base = sbase + aRow0 + mi * (16 * ROW_B) + ko;
            af[mi][0] = *reinterpret_cast<const unsigned*>(base);
            af[mi][1] = *reinterpret_cast<const unsigned*>(base + 8 * ROW_B);
            af[mi][2] = *reinterpret_cast<const unsigned*>(base + 16);
            af[mi][3] = *reinterpret_cast<const unsigned*>(base + 8 * ROW_B + 16);
        }
        #pragma unroll
        for (int ni = 0; ni < 8; ++ni) {
            const char* base = sbase + A_TILE_BYTES + bRow0 + ni * (8 * ROW_B) + ko;
            bf[ni][0] = *reinterpret_cast<const unsigned*>(base);
            bf[ni][1] = *reinterpret_cast<const unsigned*>(base + 16);
        }
        #pragma unroll
        for (int mi = 0; mi < 4; ++mi)
            #pragma unroll
            for (int ni = 0; ni < 8; ++ni)
                mma_f16(acc[mi][ni], af[mi], bf[ni]);
    };

    const int NK = KTOT / BK;

    // Prologue: stage 0 in flight
    CP_A(0, 0, 0); CP_A(0, 0, 1);
    CP_B(0, 0, 0); CP_B(0, 0, 1); CP_B(0, 0, 2); CP_B(0, 0, 3);
    CP_COMMIT();

    int s_cur = 0;

    #pragma unroll 1
    for (int kt = 0; kt < NK; ++kt) {
        asm volatile("cp.async.wait_group 0;" ::: "memory");
        __syncthreads();

        const char* sbase = smp + s_cur * STAGE_BYTES;
        const bool more = (kt + 1 < NK);
        const int  sn   = s_cur ^ 1;

        // Interleave next-stage copies into the first 6 of 8 kc chunks.
        COMPUTE_KC(sbase, 0);
        if (more) CP_A(kt + 1, sn, 0);
        COMPUTE_KC(sbase, 1);
        if (more) CP_A(kt + 1, sn, 1);
        COMPUTE_KC(sbase, 2);
        if (more) CP_B(kt + 1, sn, 0);
        COMPUTE_KC(sbase, 3);
        if (more) CP_B(kt + 1, sn, 1);
        COMPUTE_KC(sbase, 4);
        if (more) CP_B(kt + 1, sn, 2);
        COMPUTE_KC(sbase, 5);
        if (more) { CP_B(kt + 1, sn, 3); CP_COMMIT(); }
        COMPUTE_KC(sbase, 6);
        COMPUTE_KC(sbase, 7);

        s_cur = sn;
    }

    // Epilogue
    const float* bias = bias0 + (size_t)e * NTOT + bn;

    #pragma unroll
    for (int mi = 0; mi < 4; ++mi) {
        const int r0 = bm + wr * 64 + mi * 16 + g;
        #pragma unroll
        for (int ni = 0; ni < 8; ++ni) {
            const int cc = wc * 64 + ni * 8 + tq * 2;
            const float2 bv = *reinterpret_cast<const float2*>(bias + cc);
            float v00 = acc[mi][ni][0] + bv.x;
            float v01 = acc[mi][ni][1] + bv.y;
            float v10 = acc[mi][ni][2] + bv.x;
            float v11 = acc[mi][ni][3] + bv.y;
            if (GELU) {
                v00 = gelu_exact(v00); v01 = gelu_exact(v01);
                v10 = gelu_exact(v10); v11 = gelu_exact(v11);
                __half* H = Oh + (size_t)grp * CCAP * NTOT + bn;
                __half2 p0 = __floats2half2_rn(v00, v01);
                __half2 p1 = __floats2half2_rn(v10, v11);
                *reinterpret_cast<__half2*>(H + (size_t)r0 * NTOT + cc)       = p0;
                *reinterpret_cast<__half2*>(H + (size_t)(r0 + 8) * NTOT + cc) = p1;
            } else {
                float* O = Of + (size_t)grp * CCAP * NTOT + bn;
                *reinterpret_cast<float2*>(O + (size_t)r0 * NTOT + cc)       = make_float2(v00, v01);
                *reinterpret_cast<float2*>(O + (size_t)(r0 + 8) * NTOT + cc) = make_float2(v10, v11);
            }
        }
    }
}

extern "C" void kernel_launch(void* const* d_in, const int* in_sizes, int n_in,
                              void* d_out, int out_size)
{
    const float* inputs = (const float*)d_in[0];  // [4, 8192, 1024]
    const float* w1     = (const float*)d_in[1];  // [8, 4096, 1024]
    const float* b1     = (const float*)d_in[2];  // [8, 4096]
    const float* w2     = (const float*)d_in[3];  // [8, 1024, 4096]
    const float* b2     = (const float*)d_in[4];  // [8, 1024]
    float*       out    = (float*)d_out;          // [4, 8192, 1024]

    void* sp = nullptr;
    cudaGetSymbolAddress(&sp, g_scr);
    __half* in_h = (__half*)((char*)sp + OFF_IN);
    __half* w1_h = (__half*)((char*)sp + OFF_W1);
    __half* w2_h = (__half*)((char*)sp + OFF_W2);
    __half* h_h  = (__half*)((char*)sp + OFF_H);

    // Pre-pass: fp32 -> fp16 planes (each 33,554,432 elems = 8,388,608 float4)
    const int N4 = 8388608;
    to_half_kernel<<<2048, 256>>>(inputs, in_h, N4);
    to_half_kernel<<<2048, 256>>>(w1,     w1_h, N4);
    to_half_kernel<<<2048, 256>>>(w2,     w2_h, N4);

    cudaFuncSetAttribute(grouped_ffn<DFF, DMODEL, true>,
                         cudaFuncAttributeMaxDynamicSharedMemorySize, SMEM_BYTES);
    cudaFuncSetAttribute(grouped_ffn<DMODEL, DFF, false>,
                         cudaFuncAttributeMaxDynamicSharedMemorySize, SMEM_BYTES);

    // GEMM1 + gelu: h[grp][c][f]  (32 groups, M=1024, N=4096, K=1024), fp16 out
    {
        dim3 grid(DFF / BN, CCAP / BM, BATCH * NUM_E);
        grouped_ffn<DFF, DMODEL, true><<<grid, NTHREADS, SMEM_BYTES>>>(
            in_h, w1_h, b1, nullptr, h_h);
    }
    // GEMM2: out[grp][c][d]  (32 groups, M=1024, N=1024, K=4096), fp32 out
    {
        dim3 grid(DMODEL / BN, CCAP / BM, BATCH * NUM_E);
        grouped_ffn<DMODEL, DFF, false><<<grid, NTHREADS, SMEM_BYTES>>>(
            h_h, w2_h, b2, out, nullptr);
    }
}